// round 10
// baseline (speedup 1.0000x reference)
#include <cuda_runtime.h>
#include <cuda_bf16.h>
#include <cstdint>

// ============================ problem constants ============================
#define B_ROWS   2048
#define DIM      128
#define NE       100000
#define NE_PAD   100096            // 782 * 128
#define CHUNKS   782
#define SPLITS   9
#define CPS      87                // ceil(782/9)
#define ROWTILES 16
#define NCTAS    (SPLITS * ROWTILES)   // 144
#define SPLITS4  (SPLITS * 4)      // 2 warp-cols x 2 teams per split
#define SHIFT_C  96.0f
#define L2E      1.44269504088896f

// ============================ device scratch ===============================
__device__ __align__(16) __nv_bfloat16 g_A[B_ROWS * DIM];
__device__ __align__(16) __nv_bfloat16 g_E[(size_t)NE_PAD * DIM];
__device__ float g_badj[NE_PAD];         // (bias - 96) * log2(e); pad = -1e30
__device__ float g_s[B_ROWS * SPLITS4];
__device__ float g_t[B_ROWS];
__device__ unsigned int g_ctr = 0;       // monotone CTA arrival counter

// ============================ PTX helpers ==================================
__device__ __forceinline__ uint32_t smem_to_u32(const void* smem_ptr) {
    uint32_t addr;
    asm("{ .reg .u64 tmp; cvta.to.shared.u64 tmp, %1; cvt.u32.u64 %0, tmp; }"
        : "=r"(addr) : "l"(smem_ptr));
    return addr;
}

__device__ __forceinline__ float ex2(float x) {
    float y;
    asm("ex2.approx.f32 %0, %1;" : "=f"(y) : "f"(x));
    return y;
}

__device__ __forceinline__ void cp16(uint32_t saddr, const void* gaddr) {
    asm volatile("cp.async.cg.shared.global [%0], [%1], 16;"
                 :: "r"(saddr), "l"(gaddr) : "memory");
}
#define CP_COMMIT() asm volatile("cp.async.commit_group;" ::: "memory")
#define CP_WAIT0()  asm volatile("cp.async.wait_group 0;" ::: "memory")

// per-team barrier (ids 1 and 2, 256 threads each)
#define TEAM_BAR(team) \
    asm volatile("bar.sync %0, 256;" :: "r"((team) + 1) : "memory")

__device__ __forceinline__ void ldsm4(uint32_t* r, uint32_t addr) {
    asm volatile("ldmatrix.sync.aligned.m8n8.x4.shared.b16 {%0,%1,%2,%3}, [%4];"
                 : "=r"(r[0]), "=r"(r[1]), "=r"(r[2]), "=r"(r[3]) : "r"(addr));
}

__device__ __forceinline__ void mma_bf16(float& d0, float& d1, float& d2, float& d3,
                                         uint32_t a0, uint32_t a1, uint32_t a2, uint32_t a3,
                                         uint32_t b0, uint32_t b1) {
    asm volatile(
        "mma.sync.aligned.m16n8k16.row.col.f32.bf16.bf16.f32 "
        "{%0,%1,%2,%3}, {%4,%5,%6,%7}, {%8,%9}, {%0,%1,%2,%3};"
        : "+f"(d0), "+f"(d1), "+f"(d2), "+f"(d3)
        : "r"(a0), "r"(a1), "r"(a2), "r"(a3), "r"(b0), "r"(b1));
}

// ============================ SMEM layout ==================================
#define STRIDE    272                    // 256B row + 16B pad (conflict-free ldsm)
#define BTILE     34816                  // 128 * 272
#define SM_A      0
#define SM_B_BASE 34816                  // team t, buf b: + (t*2 + b) * BTILE
#define SM_BIAS   174080                 // team t, buf b: + t*1024 + b*512
#define SM_TOTAL  176128

// ============== kernel 1: fused convert + bias-fold + target ===============
__device__ __forceinline__ uint32_t pack2bf(float a, float b) {
    __nv_bfloat162 h = __floats2bfloat162_rn(a, b);
    return *(uint32_t*)&h;
}

__global__ void prep_kernel(const float* __restrict__ A,
                            const float* __restrict__ E,
                            const float* __restrict__ bias,
                            const void* __restrict__ yraw) {
    const int tid = blockIdx.x * blockDim.x + threadIdx.x;
    const int stride = gridDim.x * blockDim.x;

    // ---- target logits (exact fp32): first 2048 global warps ----
    {
        const int gwarp = tid >> 5;
        const int lane  = tid & 31;
        if (gwarp < B_ROWS) {
            const int* y32 = (const int*)yraw;
            bool is64 = (y32[1] == 0) && (y32[3] == 0) && (y32[5] == 0);
            long long idx;
            if (is64) idx = ((const long long*)yraw)[gwarp];
            else      idx = (long long)y32[gwarp];

            float4 av = ((const float4*)(A + (size_t)gwarp * DIM))[lane];
            float4 ev = ((const float4*)(E + (size_t)idx * DIM))[lane];
            float d = av.x * ev.x + av.y * ev.y + av.z * ev.z + av.w * ev.w;
            #pragma unroll
            for (int off = 16; off > 0; off >>= 1)
                d += __shfl_xor_sync(0xFFFFFFFFu, d, off);
            if (lane == 0)
                g_t[gwarp] = d + bias[idx];
        }
    }

    for (int i = tid; i < (B_ROWS * DIM) / 8; i += stride) {
        float4 v0 = ((const float4*)A)[i * 2];
        float4 v1 = ((const float4*)A)[i * 2 + 1];
        uint4 o;
        o.x = pack2bf(v0.x, v0.y);  o.y = pack2bf(v0.z, v0.w);
        o.z = pack2bf(v1.x, v1.y);  o.w = pack2bf(v1.z, v1.w);
        ((uint4*)g_A)[i] = o;
    }

    const int realE8 = (NE * DIM) / 8;
    const int padE8  = (NE_PAD * DIM) / 8;
    for (int i = tid; i < padE8; i += stride) {
        uint4 o;
        if (i < realE8) {
            float4 v0 = ((const float4*)E)[i * 2];
            float4 v1 = ((const float4*)E)[i * 2 + 1];
            o.x = pack2bf(v0.x, v0.y);  o.y = pack2bf(v0.z, v0.w);
            o.z = pack2bf(v1.x, v1.y);  o.w = pack2bf(v1.z, v1.w);
        } else {
            o = make_uint4(0, 0, 0, 0);
        }
        ((uint4*)g_E)[i] = o;
    }

    for (int i = tid; i < NE_PAD; i += stride)
        g_badj[i] = (i < NE) ? (bias[i] - SHIFT_C) * L2E : -1e30f;
}

// ===== kernel 2: two-team fused GEMM + softmax + last-CTA reduction ========
__device__ __forceinline__ void load_chunk_t(uint32_t sb, int team, int buf,
                                             int eb, int ttid) {
    uint32_t dstB = sb + SM_B_BASE + (uint32_t)(team * 2 + buf) * BTILE;
    const __nv_bfloat16* src = g_E + (size_t)eb * DIM;
    #pragma unroll
    for (int t = 0; t < 8; t++) {
        int idx = ttid + t * 256;
        int r   = idx >> 4;
        int seg = idx & 15;
        cp16(dstB + r * STRIDE + seg * 16, src + r * DIM + seg * 8);
    }
    if (ttid < 32)
        cp16(sb + SM_BIAS + team * 1024 + buf * 512 + ttid * 16,
             g_badj + eb + ttid * 4);
}

__global__ void __launch_bounds__(512, 1) main_kernel(float* __restrict__ out) {
    extern __shared__ char smem[];
    const uint32_t sb = smem_to_u32(smem);
    const int tid  = threadIdx.x;
    const int team = tid >> 8;       // 0 or 1
    const int ttid = tid & 255;      // thread id within team
    const int lane = tid & 31;
    const int wid  = ttid >> 5;      // warp within team (0..7)
    const int wm   = wid & 3;        // warp row-tile (32 rows)
    const int wn   = wid >> 2;       // warp col-tile (64 cols)
    const int split   = blockIdx.x;
    const int rowtile = blockIdx.y;

    const int start_all = split * CPS;
    const int count_all = min(CPS, CHUNKS - start_all);
    const int half0  = (count_all + 1) >> 1;
    const int tstart = start_all + (team ? half0 : 0);
    const int tcount = team ? (count_all - half0) : half0;

    // ---- whole CTA loads shared A tile; each team loads its chunk 0 ----
    {
        const __nv_bfloat16* Abase = g_A + (size_t)rowtile * 128 * DIM;
        #pragma unroll
        for (int t = 0; t < 4; t++) {
            int idx = tid + t * 512;
            int r   = idx >> 4;
            int seg = idx & 15;
            cp16(sb + SM_A + r * STRIDE + seg * 16, Abase + r * DIM + seg * 8);
        }
    }
    load_chunk_t(sb, team, 0, tstart * 128, ttid);
    CP_COMMIT();
    CP_WAIT0();
    __syncthreads();

    // ---- per-lane fragment addressing ----
    const int g = lane >> 3, i = lane & 7;
    // A frag: row = wm*32 + mi*16 + (g&1)*8 + i ; col byte = ks*32 + (g>>1)*16
    const uint32_t aofs = (uint32_t)((wm * 32 + (g & 1) * 8 + i) * STRIDE
                                     + (g >> 1) * 16);
    // B frag: row = wn*64 + q*16 + (g>>1)*8 + i ; col byte = ks*32 + (g&1)*16
    const uint32_t bofs = (uint32_t)((wn * 64 + (g >> 1) * 8 + i) * STRIDE
                                     + (g & 1) * 16);
    const int bcol = wn * 64 + (lane & 3) * 2;

    float s[4] = {0.f, 0.f, 0.f, 0.f};

    for (int c = 0; c < tcount; ++c) {
        if (c + 1 < tcount)
            load_chunk_t(sb, team, (c + 1) & 1, (tstart + c + 1) * 128, ttid);
        CP_COMMIT();

        const uint32_t sBcur = sb + SM_B_BASE + (uint32_t)(team * 2 + (c & 1)) * BTILE;
        const float* biasp  = (const float*)(smem + SM_BIAS + team * 1024
                                             + (c & 1) * 512);

        // ---- 128x128x128 GEMM (A frags reloaded per ks; saves 64 regs) ----
        float acc[2][8][4];
        #pragma unroll
        for (int mi = 0; mi < 2; mi++)
            #pragma unroll
            for (int j = 0; j < 8; j++)
                #pragma unroll
                for (int e = 0; e < 4; e++)
                    acc[mi][j][e] = 0.f;

        #pragma unroll
        for (int ks = 0; ks < 8; ks++) {
            uint32_t af[2][4];
            ldsm4(af[0], sb + SM_A + aofs + ks * 32);               // mi 0
            ldsm4(af[1], sb + SM_A + aofs + 16 * STRIDE + ks * 32); // mi 1
            uint32_t bb[8][2];
            #pragma unroll
            for (int q = 0; q < 4; q++) {
                uint32_t r4[4];
                ldsm4(r4, sBcur + bofs + q * 16 * STRIDE + ks * 32);
                bb[2 * q][0]     = r4[0];
                bb[2 * q][1]     = r4[1];
                bb[2 * q + 1][0] = r4[2];
                bb[2 * q + 1][1] = r4[3];
            }
            #pragma unroll
            for (int mi = 0; mi < 2; mi++)
                #pragma unroll
                for (int j = 0; j < 8; j++)
                    mma_bf16(acc[mi][j][0], acc[mi][j][1], acc[mi][j][2], acc[mi][j][3],
                             af[mi][0], af[mi][1], af[mi][2], af[mi][3],
                             bb[j][0], bb[j][1]);
        }

        // ---- epilogue: per-j transient bias; s += exp2(acc*L2E + badj) ----
        #pragma unroll
        for (int j = 0; j < 8; j++) {
            float2 bz = *(const float2*)(biasp + bcol + j * 8);
            s[0] += ex2(fmaf(acc[0][j][0], L2E, bz.x))
                  + ex2(fmaf(acc[0][j][1], L2E, bz.y));
            s[1] += ex2(fmaf(acc[0][j][2], L2E, bz.x))
                  + ex2(fmaf(acc[0][j][3], L2E, bz.y));
            s[2] += ex2(fmaf(acc[1][j][0], L2E, bz.x))
                  + ex2(fmaf(acc[1][j][1], L2E, bz.y));
            s[3] += ex2(fmaf(acc[1][j][2], L2E, bz.x))
                  + ex2(fmaf(acc[1][j][3], L2E, bz.y));
        }

        CP_WAIT0();
        TEAM_BAR(team);    // team-local: the other team keeps running
    }

    // ---- reduce across lane quads, write partials ----
    #pragma unroll
    for (int slot = 0; slot < 4; slot++) {
        s[slot] += __shfl_xor_sync(0xFFFFFFFFu, s[slot], 1);
        s[slot] += __shfl_xor_sync(0xFFFFFFFFu, s[slot], 2);
    }

    if ((lane & 3) == 0) {
        const int part = (split * 2 + wn) * 2 + team;
        #pragma unroll
        for (int slot = 0; slot < 4; slot++) {
            int row = rowtile * 128 + wm * 32 + (slot >> 1) * 16 + (lane >> 2)
                    + (slot & 1) * 8;
            g_s[row * SPLITS4 + part] = s[slot];
        }
    }

    // ---- last-arriving CTA performs the final merge + mean NLL ----
    __threadfence();
    __shared__ unsigned int sIsLast;
    __syncthreads();
    if (tid == 0) {
        unsigned int v = atomicAdd(&g_ctr, 1u);
        sIsLast = ((v % NCTAS) == (NCTAS - 1)) ? 1u : 0u;
    }
    __syncthreads();
    if (sIsLast) {
        float* red = (float*)smem;
        float acc = 0.f;
        for (int row = tid; row < B_ROWS; row += 512) {
            float ssum = 0.f;
            #pragma unroll
            for (int sp = 0; sp < SPLITS4; ++sp)
                ssum += g_s[row * SPLITS4 + sp];
            acc += SHIFT_C + logf(ssum) - g_t[row];
        }
        red[tid] = acc;
        __syncthreads();
        #pragma unroll
        for (int off = 256; off > 0; off >>= 1) {
            if (tid < off) red[tid] += red[tid + off];
            __syncthreads();
        }
        if (tid == 0) out[0] = red[0] / (float)B_ROWS;
    }
}

// ============================ launch ======================================
extern "C" void kernel_launch(void* const* d_in, const int* in_sizes, int n_in,
                              void* d_out, int out_size) {
    const float* A    = (const float*)d_in[0];   // [2048, 128]
    const float* E    = (const float*)d_in[1];   // [100000, 128]
    const float* bias = (const float*)d_in[2];   // [100000]
    const void*  y    = d_in[3];                 // [2048] int64 or int32

    cudaFuncSetAttribute(main_kernel,
                         cudaFuncAttributeMaxDynamicSharedMemorySize, SM_TOTAL);

    prep_kernel<<<2048, 256>>>(A, E, bias, y);
    main_kernel<<<dim3(SPLITS, ROWTILES), 512, SM_TOTAL>>>((float*)d_out);
}